// round 7
// baseline (speedup 1.0000x reference)
#include <cuda_runtime.h>
#include <cmath>

// ---------------------------------------------------------------------------
// SceneSegCNNTRM round 4 (= round 3 resubmit, static-guard removed):
// fragment-ordered tf32 mma GEMM, conv folded into K, smem-cached pooling,
// custom cls head.
// ---------------------------------------------------------------------------

#define MROWS   4096
#define NB      1024
#define DIN     2048
#define DMODEL  640
#define NLAYER  6
#define QKVN    1920

__device__ __align__(256) float g_pooled[MROWS * DIN];
__device__ __align__(256) float g_out   [MROWS * DMODEL];
__device__ __align__(256) float g_qkv   [MROWS * QKVN];
__device__ __align__(256) float g_wqkv  [NLAYER * DMODEL * QKVN];
__device__ __align__(256) float g_ctx   [MROWS * DMODEL];
__device__ __align__(256) float g_tmp   [MROWS * DMODEL];
__device__ __align__(256) float g_ff    [MROWS * 128];
__device__ __align__(256) float g_h     [MROWS * 256];

// ---------------------------------------------------------------------------
__global__ __launch_bounds__(256) void pack_qkv_kernel(
    const float* __restrict__ Wq, const float* __restrict__ Wk,
    const float* __restrict__ Wv, float* __restrict__ out)
{
    const int i = blockIdx.x * 256 + threadIdx.x;
    if (i >= NLAYER * DMODEL * QKVN) return;
    const int n = i % QKVN;
    const int k = (i / QKVN) % DMODEL;
    const int l = i / (QKVN * DMODEL);
    const float* W = (n < DMODEL) ? Wq : (n < 2 * DMODEL) ? Wk : Wv;
    out[i] = W[(size_t)l * DMODEL * DMODEL + (size_t)k * DMODEL + (n % DMODEL)];
}

// ---------------------------------------------------------------------------
// pool + cos-sim: x window cached in 64KB dynamic smem (single global read).
// ---------------------------------------------------------------------------
__global__ __launch_bounds__(256) void pool_sim_kernel(
    const float* __restrict__ x,
    const float* __restrict__ cos_w, const float* __restrict__ cos_b,
    const float* __restrict__ attn_w, const float* __restrict__ attn_b,
    float* __restrict__ pooled, float* __restrict__ outbuf)
{
    extern __shared__ float xs[];   // [8][2048]
    const int m   = blockIdx.x;
    const int tid = threadIdx.x;
    const float* xr = x + (size_t)m * 8 * DIN;

#pragma unroll
    for (int r = 0; r < 16; r++) {
        const int idx = tid + r * 256;
        *reinterpret_cast<float4*>(xs + idx * 4) =
            *reinterpret_cast<const float4*>(xr + idx * 4);
    }
    __syncthreads();

    float g12[16], g11[10], g22[10], sw[8], ad[8];
#pragma unroll
    for (int i = 0; i < 16; i++) g12[i] = 0.f;
#pragma unroll
    for (int i = 0; i < 10; i++) { g11[i] = 0.f; g22[i] = 0.f; }
#pragma unroll
    for (int i = 0; i < 8; i++)  { sw[i] = 0.f; ad[i] = 0.f; }

    for (int d = tid; d < DIN; d += 256) {
        float xv[8];
#pragma unroll
        for (int w = 0; w < 8; w++) xv[w] = xs[w * DIN + d];
        const float aw = attn_w[d];
#pragma unroll
        for (int w = 0; w < 8; w++) { sw[w] += xv[w]; ad[w] += xv[w] * aw; }
#pragma unroll
        for (int i = 0; i < 4; i++)
#pragma unroll
            for (int j = 0; j < 4; j++)
                g12[i * 4 + j] += xv[i] * xv[4 + j];
#pragma unroll
        for (int i = 0; i < 4; i++)
#pragma unroll
            for (int j = i; j < 4; j++) {
                const int t = i * (7 - i) / 2 + j;
                g11[t] += xv[i] * xv[j];
                g22[t] += xv[4 + i] * xv[4 + j];
            }
    }

    __shared__ float red[52][8];
    __shared__ float fin[52];
    __shared__ float aprob[8];
    const int lane = tid & 31, wid = tid >> 5;

#define WREDUCE(arr, n, off)                                              \
    _Pragma("unroll")                                                     \
    for (int i = 0; i < n; i++) {                                         \
        float v = arr[i];                                                 \
        _Pragma("unroll")                                                 \
        for (int o = 16; o; o >>= 1) v += __shfl_xor_sync(0xffffffffu, v, o); \
        if (lane == 0) red[off + i][wid] = v;                             \
    }
    WREDUCE(g12, 16, 0)
    WREDUCE(g11, 10, 16)
    WREDUCE(g22, 10, 26)
    WREDUCE(sw,   8, 36)
    WREDUCE(ad,   8, 44)
#undef WREDUCE
    __syncthreads();
    if (tid < 52) {
        float t = 0.f;
#pragma unroll
        for (int w = 0; w < 8; w++) t += red[tid][w];
        fin[tid] = t;
    }
    __syncthreads();

    if (tid == 0) {
        const float ab = attn_b[0];
        float sc[8], mx = -1e30f;
#pragma unroll
        for (int w = 0; w < 8; w++) { sc[w] = fin[44 + w] + ab; mx = fmaxf(mx, sc[w]); }
        float s = 0.f;
#pragma unroll
        for (int w = 0; w < 8; w++) { sc[w] = expf(sc[w] - mx); s += sc[w]; }
        const float inv = 1.f / s;
#pragma unroll
        for (int w = 0; w < 8; w++) aprob[w] = sc[w] * inv;
    }

    if (tid < 128) {
        float cw[4];
#pragma unroll
        for (int w = 0; w < 4; w++) cw[w] = cos_w[tid * 4 + w];
        const float cb = cos_b[tid];
        float d12 = 0.f, q1 = 0.f, q2 = 0.f, cs1 = 0.f, cs2 = 0.f;
#pragma unroll
        for (int i = 0; i < 4; i++)
#pragma unroll
            for (int j = 0; j < 4; j++)
                d12 += cw[i] * cw[j] * fin[i * 4 + j];
#pragma unroll
        for (int i = 0; i < 4; i++)
#pragma unroll
            for (int j = i; j < 4; j++) {
                const int t = i * (7 - i) / 2 + j;
                const float c2 = cw[i] * cw[j] * ((i == j) ? 1.f : 2.f);
                q1 += c2 * fin[16 + t];
                q2 += c2 * fin[26 + t];
            }
#pragma unroll
        for (int w = 0; w < 4; w++) {
            cs1 += cw[w] * fin[36 + w];
            cs2 += cw[w] * fin[40 + w];
        }
        d12 += cb * (cs1 + cs2) + (float)DIN * cb * cb;
        q1  += 2.f * cb * cs1 + (float)DIN * cb * cb;
        q2  += 2.f * cb * cs2 + (float)DIN * cb * cb;
        const float n1 = fmaxf(sqrtf(q1), 1e-8f);
        const float n2 = fmaxf(sqrtf(q2), 1e-8f);
        outbuf[(size_t)m * DMODEL + 512 + tid] = d12 / (n1 * n2);
    }
    __syncthreads();

    float a[8];
#pragma unroll
    for (int w = 0; w < 8; w++) a[w] = aprob[w];
    for (int d = tid; d < DIN; d += 256) {
        float p = 0.f;
#pragma unroll
        for (int w = 0; w < 8; w++) p += a[w] * xs[w * DIN + d];
        pooled[(size_t)m * DIN + d] = p;
    }
}

// ---------------------------------------------------------------------------
// tf32 tensor-core GEMM, fragment-ordered smem, BK=16 double-buffered.
//  - CONV=true: virtual K' = 3*Kreal; tap t = k'/Kreal shifts A rows (+t-1)
//    within each NB-row batch; B gathered from (Cout, Cin, 3) weights.
//  - Requires: M%BM==0, N%BN==0, K%16==0, non-conv B has unit n-stride.
//  - flags: bit0 = relu.
// ---------------------------------------------------------------------------
__device__ __forceinline__ float to_tf32(float x) {
    asm("cvt.rna.tf32.f32 %0, %0;" : "+f"(x));
    return x;
}

template<int BM, int BN, bool CONV>
__global__ __launch_bounds__(256) void gemm_tc(
    const float* __restrict__ A, int lda,
    const float* __restrict__ B, int ldbK,
    const float* __restrict__ bias,
    float* __restrict__ C, int ldc,
    int M, int N, int K, int klog2, int flags)
{
    constexpr int MTB = BM / 16;
    constexpr int NTB = BN / 8;
    constexpr int WARPS_N = 8 / (BM / 32);
    constexpr int WN  = BN / WARPS_N;
    constexpr int NT  = WN / 8;
    constexpr int A4  = BM * 4 / 256;
    constexpr int B4  = BN * 4 / 256;
    constexpr int BSC = BN * 16 / 256;

    __shared__ float As[2][BM * 16];
    __shared__ float Bs[2][BN * 16];

    const int tid  = threadIdx.x;
    const int lane = tid & 31;
    const int w    = tid >> 5;
    const int bm   = blockIdx.y * BM;
    const int bn   = blockIdx.x * BN;
    const int mtw  = (w / WARPS_N) * 2;
    const int ntw  = ((w % WARPS_N) * WN) >> 3;

    float acc[2][NT][4];
#pragma unroll
    for (int i = 0; i < 2; i++)
#pragma unroll
        for (int j = 0; j < NT; j++)
#pragma unroll
            for (int r = 0; r < 4; r++) acc[i][j][r] = 0.f;

    float4 ra[A4];
    float4 rbv[B4];
    float  rbs[BSC];
    const int kmask = CONV ? ((1 << klog2) - 1) : 0;

    auto loadA = [&](int k0) {
        const int t   = CONV ? (k0 >> klog2) : 0;
        const int kr0 = CONV ? (k0 & kmask) : k0;
#pragma unroll
        for (int r = 0; r < A4; r++) {
            const int idx = tid + r * 256;
            const int mm  = idx >> 2, cg = (idx & 3) << 2;
            const int gm  = bm + mm;
            float4 v = make_float4(0.f, 0.f, 0.f, 0.f);
            if (!CONV) {
                v = *reinterpret_cast<const float4*>(A + (size_t)gm * lda + kr0 + cg);
            } else if ((unsigned)((gm & (NB - 1)) + t - 1) < (unsigned)NB) {
                v = *reinterpret_cast<const float4*>(A + (size_t)(gm + t - 1) * lda + kr0 + cg);
            }
            ra[r] = v;
        }
    };
    auto storeA = [&](int st) {
#pragma unroll
        for (int r = 0; r < A4; r++) {
            const int idx = tid + r * 256;
            const int mm  = idx >> 2, cg = (idx & 3) << 2;
            const int kb  = cg >> 3, kh = (cg >> 2) & 1;
            const int mtile = mm >> 4, g = mm & 7, hi = (mm >> 3) & 1;
            float* p = &As[st][(kb * MTB + mtile) * 128 + g * 16 + hi + 2 * kh];
            p[0]  = to_tf32(ra[r].x);
            p[4]  = to_tf32(ra[r].y);
            p[8]  = to_tf32(ra[r].z);
            p[12] = to_tf32(ra[r].w);
        }
    };
    auto loadB = [&](int k0) {
        if (!CONV) {
#pragma unroll
            for (int r = 0; r < B4; r++) {
                const int idx = tid + r * 256;
                const int kk  = idx / (BN / 4);
                const int nn  = (idx % (BN / 4)) * 4;
                rbv[r] = *reinterpret_cast<const float4*>(
                    B + (size_t)(k0 + kk) * ldbK + bn + nn);
            }
        } else {
            const int t   = k0 >> klog2;
            const int kr0 = k0 & kmask;
            const int kr3 = 3 << klog2;
#pragma unroll
            for (int r = 0; r < BSC; r++) {
                const int idx = tid + r * 256;
                const int kk  = idx / BN;
                const int nn  = idx % BN;
                rbs[r] = B[(size_t)(bn + nn) * kr3 + (size_t)(kr0 + kk) * 3 + t];
            }
        }
    };
    auto storeB = [&](int st) {
        if (!CONV) {
#pragma unroll
            for (int r = 0; r < B4; r++) {
                const int idx = tid + r * 256;
                const int kk  = idx / (BN / 4);
                const int nn  = (idx % (BN / 4)) * 4;
                const int kb  = kk >> 3, tg = kk & 3, kh = (kk >> 2) & 1;
                const float vv[4] = { rbv[r].x, rbv[r].y, rbv[r].z, rbv[r].w };
#pragma unroll
                for (int j = 0; j < 4; j++) {
                    const int n = nn + j;
                    Bs[st][(kb * NTB + (n >> 3)) * 64 + ((n & 7) * 4 + tg) * 2 + kh]
                        = to_tf32(vv[j]);
                }
            }
        } else {
#pragma unroll
            for (int r = 0; r < BSC; r++) {
                const int idx = tid + r * 256;
                const int kk  = idx / BN;
                const int n   = idx % BN;
                const int kb  = kk >> 3, tg = kk & 3, kh = (kk >> 2) & 1;
                Bs[st][(kb * NTB + (n >> 3)) * 64 + ((n & 7) * 4 + tg) * 2 + kh]
                    = to_tf32(rbs[r]);
            }
        }
    };

    loadA(0); loadB(0);
    storeA(0); storeB(0);
    __syncthreads();

    int st = 0;
    for (int k0 = 0; k0 < K; k0 += 16) {
        const bool more = (k0 + 16) < K;
        if (more) { loadA(k0 + 16); loadB(k0 + 16); }

#pragma unroll
        for (int kb = 0; kb < 2; kb++) {
            float4 af[2];
            float2 bf[NT];
#pragma unroll
            for (int mi = 0; mi < 2; mi++)
                af[mi] = *reinterpret_cast<const float4*>(
                    &As[st][(kb * MTB + mtw + mi) * 128 + lane * 4]);
#pragma unroll
            for (int nj = 0; nj < NT; nj++)
                bf[nj] = *reinterpret_cast<const float2*>(
                    &Bs[st][(kb * NTB + ntw + nj) * 64 + lane * 2]);
#pragma unroll
            for (int mi = 0; mi < 2; mi++)
#pragma unroll
                for (int nj = 0; nj < NT; nj++)
                    asm volatile(
                        "mma.sync.aligned.m16n8k8.row.col.f32.tf32.tf32.f32 "
                        "{%0,%1,%2,%3}, {%4,%5,%6,%7}, {%8,%9}, {%0,%1,%2,%3};\n"
                        : "+f"(acc[mi][nj][0]), "+f"(acc[mi][nj][1]),
                          "+f"(acc[mi][nj][2]), "+f"(acc[mi][nj][3])
                        : "r"(__float_as_uint(af[mi].x)), "r"(__float_as_uint(af[mi].y)),
                          "r"(__float_as_uint(af[mi].z)), "r"(__float_as_uint(af[mi].w)),
                          "r"(__float_as_uint(bf[nj].x)), "r"(__float_as_uint(bf[nj].y)));
        }

        if (more) {
            storeA(st ^ 1); storeB(st ^ 1);
            __syncthreads();
            st ^= 1;
        }
    }

    const int g  = lane >> 2, tg = lane & 3;
#pragma unroll
    for (int mi = 0; mi < 2; mi++) {
        const int r0 = bm + (mtw + mi) * 16 + g;
#pragma unroll
        for (int nj = 0; nj < NT; nj++) {
            const int c0 = bn + (ntw + nj) * 8 + tg * 2;
#pragma unroll
            for (int hh = 0; hh < 2; hh++) {
                float* crow = C + (size_t)(r0 + hh * 8) * ldc;
#pragma unroll
                for (int cc = 0; cc < 2; cc++) {
                    float v = acc[mi][nj][hh * 2 + cc];
                    if (bias) v += bias[c0 + cc];
                    if (flags & 1) v = fmaxf(v, 0.f);
                    crow[c0 + cc] = v;
                }
            }
        }
    }
}

// ---------------------------------------------------------------------------
// Banded local attention (|i-j|<=1), one warp per (token, head), d_head=80.
// ---------------------------------------------------------------------------
__global__ __launch_bounds__(256) void banded_attn_kernel(
    const float* __restrict__ qkv, float* __restrict__ ctx)
{
    const int gw   = (blockIdx.x * 256 + threadIdx.x) >> 5;
    const int lane = threadIdx.x & 31;
    if (gw >= MROWS * 8) return;
    const int m = gw >> 3;
    const int h = gw & 7;
    const int n = m & (NB - 1);
    const float scale = 0.11180339887498949f;

    const float* qp = qkv + (size_t)m * QKVN + h * 80;
    const float qv0 = qp[lane], qv1 = qp[lane + 32];
    const float qv2 = (lane < 16) ? qp[lane + 64] : 0.f;

    float s[3];
    bool  val[3];
#pragma unroll
    for (int j = 0; j < 3; j++) {
        const int nn = n + j - 1;
        val[j] = (nn >= 0 && nn < NB);
        float acc = 0.f;
        if (val[j]) {
            const float* kp = qkv + (size_t)(m + j - 1) * QKVN + DMODEL + h * 80;
            acc = qv0 * kp[lane] + qv1 * kp[lane + 32];
            if (lane < 16) acc += qv2 * kp[lane + 64];
        }
#pragma unroll
        for (int o = 16; o; o >>= 1) acc += __shfl_xor_sync(0xffffffffu, acc, o);
        s[j] = val[j] ? acc * scale : -1e30f;
    }

    const float mx = fmaxf(s[0], fmaxf(s[1], s[2]));
    float e[3], sum = 0.f;
#pragma unroll
    for (int j = 0; j < 3; j++) {
        e[j] = val[j] ? expf(s[j] - mx) : 0.f;
        sum += e[j];
    }
    const float inv = 1.f / sum;

    float o0 = 0.f, o1 = 0.f, o2 = 0.f;
#pragma unroll
    for (int j = 0; j < 3; j++) {
        if (!val[j]) continue;
        const float p = e[j] * inv;
        const float* vp = qkv + (size_t)(m + j - 1) * QKVN + 2 * DMODEL + h * 80;
        o0 += p * vp[lane];
        o1 += p * vp[lane + 32];
        if (lane < 16) o2 += p * vp[lane + 64];
    }
    float* cp = ctx + (size_t)m * DMODEL + h * 80;
    cp[lane] = o0;
    cp[lane + 32] = o1;
    if (lane < 16) cp[lane + 64] = o2;
}

// ---------------------------------------------------------------------------
__global__ __launch_bounds__(256) void residual_ln_kernel(
    float* __restrict__ out, const float* __restrict__ add,
    const float* __restrict__ g, const float* __restrict__ b)
{
    const int m = blockIdx.x;
    const int tid = threadIdx.x;
    const int lane = tid & 31, wid = tid >> 5;
    __shared__ float red[8];
    __shared__ float mean_s, rstd_s;

    float v[3];
    float s = 0.f;
#pragma unroll
    for (int i = 0; i < 3; i++) {
        const int d = tid + i * 256;
        float t = 0.f;
        if (d < DMODEL) t = out[(size_t)m * DMODEL + d] + add[(size_t)m * DMODEL + d];
        v[i] = t;
        s += t;
    }
#pragma unroll
    for (int o = 16; o; o >>= 1) s += __shfl_xor_sync(0xffffffffu, s, o);
    if (lane == 0) red[wid] = s;
    __syncthreads();
    if (tid == 0) {
        float t = 0.f;
#pragma unroll
        for (int w = 0; w < 8; w++) t += red[w];
        mean_s = t / (float)DMODEL;
    }
    __syncthreads();
    const float mean = mean_s;

    float vs = 0.f;
#pragma unroll
    for (int i = 0; i < 3; i++) {
        const int d = tid + i * 256;
        if (d < DMODEL) { const float dd = v[i] - mean; vs += dd * dd; }
    }
#pragma unroll
    for (int o = 16; o; o >>= 1) vs += __shfl_xor_sync(0xffffffffu, vs, o);
    __syncthreads();
    if (lane == 0) red[wid] = vs;
    __syncthreads();
    if (tid == 0) {
        float t = 0.f;
#pragma unroll
        for (int w = 0; w < 8; w++) t += red[w];
        rstd_s = rsqrtf(t / (float)DMODEL + 1e-5f);
    }
    __syncthreads();
    const float rstd = rstd_s;
#pragma unroll
    for (int i = 0; i < 3; i++) {
        const int d = tid + i * 256;
        if (d < DMODEL)
            out[(size_t)m * DMODEL + d] = (v[i] - mean) * rstd * g[d] + b[d];
    }
}

// ---------------------------------------------------------------------------
// cls head: logits[m, 0..1] = h[m, :256] @ cls_w + cls_b. One warp per row.
// ---------------------------------------------------------------------------
__global__ __launch_bounds__(256) void cls_kernel(
    const float* __restrict__ h, const float* __restrict__ w,
    const float* __restrict__ b, float* __restrict__ out)
{
    const int gw   = (blockIdx.x * 256 + threadIdx.x) >> 5;
    const int lane = threadIdx.x & 31;
    if (gw >= MROWS) return;
    float a0 = 0.f, a1 = 0.f;
#pragma unroll
    for (int i = 0; i < 8; i++) {
        const int k = lane + i * 32;
        const float hv = h[(size_t)gw * 256 + k];
        a0 += hv * w[k * 2];
        a1 += hv * w[k * 2 + 1];
    }
#pragma unroll
    for (int o = 16; o; o >>= 1) {
        a0 += __shfl_xor_sync(0xffffffffu, a0, o);
        a1 += __shfl_xor_sync(0xffffffffu, a1, o);
    }
    if (lane == 0) {
        out[(size_t)gw * 2]     = a0 + b[0];
        out[(size_t)gw * 2 + 1] = a1 + b[1];
    }
}

// ---------------------------------------------------------------------------
extern "C" void kernel_launch(void* const* d_in, const int* in_sizes, int n_in,
                              void* d_out, int out_size)
{
    const float* x       = (const float*)d_in[0];
    const float* cos_w   = (const float*)d_in[2];
    const float* cos_b   = (const float*)d_in[3];
    const float* attn_w  = (const float*)d_in[4];
    const float* attn_b  = (const float*)d_in[5];
    const float* conv1_w = (const float*)d_in[6];
    const float* conv1_b = (const float*)d_in[7];
    const float* conv2_w = (const float*)d_in[8];
    const float* conv2_b = (const float*)d_in[9];
    const float* Wq      = (const float*)d_in[10];
    const float* Wk      = (const float*)d_in[11];
    const float* Wv      = (const float*)d_in[12];
    const float* Wo      = (const float*)d_in[13];
    const float* ln1_g   = (const float*)d_in[14];
    const float* ln1_b   = (const float*)d_in[15];
    const float* ff1_w   = (const float*)d_in[16];
    const float* ff1_b   = (const float*)d_in[17];
    const float* ff2_w   = (const float*)d_in[18];
    const float* ff2_b   = (const float*)d_in[19];
    const float* ln2_g   = (const float*)d_in[20];
    const float* ln2_b   = (const float*)d_in[21];
    const float* fc_w    = (const float*)d_in[22];
    const float* fc_b    = (const float*)d_in[23];
    const float* cls_w   = (const float*)d_in[24];
    const float* cls_b   = (const float*)d_in[25];
    float* logits = (float*)d_out;

    float *pooled, *obuf, *qkvb, *wqkv, *ctxb, *tmpb, *ffb, *hb;
    cudaGetSymbolAddress((void**)&pooled, g_pooled);
    cudaGetSymbolAddress((void**)&obuf,   g_out);
    cudaGetSymbolAddress((void**)&qkvb,   g_qkv);
    cudaGetSymbolAddress((void**)&wqkv,   g_wqkv);
    cudaGetSymbolAddress((void**)&ctxb,   g_ctx);
    cudaGetSymbolAddress((void**)&tmpb,   g_tmp);
    cudaGetSymbolAddress((void**)&ffb,    g_ff);
    cudaGetSymbolAddress((void**)&hb,     g_h);

    // idempotent, deterministic, not a stream op (capture-safe); no static guard
    cudaFuncSetAttribute(pool_sim_kernel,
                         cudaFuncAttributeMaxDynamicSharedMemorySize, 65536);

    // 0. pack QKV weights
    {
        const int tot = NLAYER * DMODEL * QKVN;
        pack_qkv_kernel<<<(tot + 255) / 256, 256>>>(Wq, Wk, Wv, wqkv);
    }

    // 1. pooling + cos-sim
    pool_sim_kernel<<<MROWS, 256, 65536>>>(x, cos_w, cos_b, attn_w, attn_b,
                                           pooled, obuf);

    // 2. conv1 as one GEMM: K' = 3*2048 = 6144, tap folded into K
    gemm_tc<128, 64, true><<<dim3(4, 32), 256>>>(
        pooled, DIN, conv1_w, 0, conv1_b, obuf, DMODEL,
        MROWS, 256, 3 * DIN, 11, 1 /*relu*/);

    // 3. conv2: K' = 3*256 = 768
    gemm_tc<128, 64, true><<<dim3(4, 32), 256>>>(
        obuf, DMODEL, conv2_w, 0, conv2_b, obuf + 256, DMODEL,
        MROWS, 256, 3 * 256, 8, 1 /*relu*/);

    // 4. transformer layers
    for (int l = 0; l < NLAYER; l++) {
        gemm_tc<128, 128, false><<<dim3(15, 32), 256>>>(
            obuf, DMODEL, wqkv + (size_t)l * DMODEL * QKVN, QKVN,
            nullptr, qkvb, QKVN, MROWS, QKVN, DMODEL, 0, 0);

        banded_attn_kernel<<<MROWS, 256>>>(qkvb, ctxb);

        gemm_tc<128, 128, false><<<dim3(5, 32), 256>>>(
            ctxb, DMODEL, Wo + (size_t)l * DMODEL * DMODEL, DMODEL,
            nullptr, tmpb, DMODEL, MROWS, DMODEL, DMODEL, 0, 0);
        residual_ln_kernel<<<MROWS, 256>>>(obuf, tmpb,
                                           ln1_g + l * DMODEL, ln1_b + l * DMODEL);

        gemm_tc<64, 64, false><<<dim3(2, 64), 256>>>(
            obuf, DMODEL, ff1_w + (size_t)l * DMODEL * 128, 128,
            ff1_b + l * 128, ffb, 128, MROWS, 128, DMODEL, 0, 1 /*relu*/);
        gemm_tc<128, 128, false><<<dim3(5, 32), 256>>>(
            ffb, 128, ff2_w + (size_t)l * 128 * DMODEL, DMODEL,
            ff2_b + l * DMODEL, tmpb, DMODEL, MROWS, DMODEL, 128, 0, 0);
        residual_ln_kernel<<<MROWS, 256>>>(obuf, tmpb,
                                           ln2_g + l * DMODEL, ln2_b + l * DMODEL);
    }

    // 5. head
    gemm_tc<128, 64, false><<<dim3(4, 32), 256>>>(
        obuf, DMODEL, fc_w, 256, fc_b, hb, 256, MROWS, 256, DMODEL, 0, 1 /*relu*/);
    cls_kernel<<<(MROWS * 32 + 255) / 256, 256>>>(hb, cls_w, cls_b, logits);
}